// round 13
// baseline (speedup 1.0000x reference)
#include <cuda_runtime.h>
#include <cstdint>

#define POOL 14
#define IMG_H 200
#define IMG_W 200
#define IMG_C 1024
#define NUM_ROIS 512

#define NCHUNK 4                       // 256-ch slices -> 41MB image slice, L2-resident
#define CHUNK_FLOATS (IMG_C / NCHUNK)  // 256 floats per cell-chunk
#define WARPS_PER_BLOCK 8
#define THREADS (WARPS_PER_BLOCK * 32) // 256

typedef unsigned long long u64;

// ---- packed f32x2 helpers (sm_103a) ----
__device__ __forceinline__ u64 pk2(float a, float b) {
    u64 r;
    asm("mov.b64 %0, {%1, %2};" : "=l"(r) : "f"(a), "f"(b));
    return r;
}
__device__ __forceinline__ u64 mul2(u64 a, u64 b) {
    u64 r;
    asm("mul.rn.f32x2 %0, %1, %2;" : "=l"(r) : "l"(a), "l"(b));
    return r;
}
__device__ __forceinline__ u64 fma2(u64 a, u64 b, u64 c) {
    u64 r;
    asm("fma.rn.f32x2 %0, %1, %2, %3;" : "=l"(r) : "l"(a), "l"(b), "l"(c));
    return r;
}

// 256-bit L2-only load: 4x packed f32x2 = 8 floats = 32B. One such load by
// a full warp covers 1KB contiguous (8x128B lines, perfectly coalesced).
__device__ __forceinline__ void ldg256_cg(const float* p,
                                          u64& r0, u64& r1, u64& r2, u64& r3) {
    asm volatile("ld.global.cg.v4.b64 {%0,%1,%2,%3}, [%4];"
                 : "=l"(r0), "=l"(r1), "=l"(r2), "=l"(r3) : "l"(p));
}

// 256-bit streaming store (evict-first: protects the L2-resident image slice).
__device__ __forceinline__ void stg256_cs(float* p, u64 r0, u64 r1, u64 r2, u64 r3) {
    asm volatile("st.global.cs.v4.b64 [%0], {%1,%2,%3,%4};"
                 :: "l"(p), "l"(r0), "l"(r1), "l"(r2), "l"(r3) : "memory");
}

// grid = (cells/8, NCHUNK), one WARP per cell-chunk. Chunk-outer keeps each
// 41MB channel slice L2-resident (~472MB DRAM, measured). Per warp: <=4
// LDG.256 + 1 STG.256 for the whole 1KB chunk -> ~45% fewer issued
// instructions than R12; zero-weight corner skips are warp-uniform (no
// divergence, unlike R12's 2-cells-per-warp layout).
__global__ void __launch_bounds__(THREADS, 4)
roi_resize_kernel(const float* __restrict__ img,
                  const int* __restrict__ rois,
                  float* __restrict__ out)
{
    const int warp = threadIdx.x >> 5;              // 0..7: cell within block
    const int lane = threadIdx.x & 31;              // channel lane (8 floats)

    const int idx  = blockIdx.x * WARPS_PER_BLOCK + warp;  // 0..100351
    const int roi  = idx / (POOL * POOL);
    const int cell = idx - roi * (POOL * POOL);
    const int py   = cell / POOL;
    const int px   = cell - py * POOL;

    const int chunk_off = blockIdx.y * CHUNK_FLOATS;

    const int4 box = reinterpret_cast<const int4*>(rois)[roi];
    const int bx = box.x, by = box.y, bw = box.z, bh = box.w;

    // Match reference math: fraction from UNclipped floor.
    const float sy = (float)py * ((float)bh / (float)POOL);
    const float sx = (float)px * ((float)bw / (float)POOL);
    const int y0 = (int)floorf(sy);
    const int x0 = (int)floorf(sx);
    const float wy = sy - (float)y0;
    const float wx = sx - (float)x0;

    // Warp-uniform: one cell per warp, so these branches never diverge.
    const bool need_x1 = (wx != 0.0f);
    const bool need_y1 = (wy != 0.0f);

    const int y0c = min(max(y0, 0), bh - 1);
    const int y1c = min(max(y0 + 1, 0), bh - 1);
    const int x0c = min(max(x0, 0), bw - 1);
    const int x1c = min(max(x0 + 1, 0), bw - 1);

    const int iy0 = by + y0c;
    const int iy1 = by + y1c;
    const int ix0 = bx + x0c;
    const int ix1 = bx + x1c;

    const u64 wx2   = pk2(wx, wx);
    const u64 omwx2 = pk2(1.0f - wx, 1.0f - wx);
    const u64 wy2   = pk2(wy, wy);
    const u64 omwy2 = pk2(1.0f - wy, 1.0f - wy);

    // Lane offset folded into the base once: lane*8 floats = lane*32B.
    const float* base = img + chunk_off + lane * 8;
    const float* __restrict__ p00 = base + ((size_t)iy0 * IMG_W + ix0) * IMG_C;
    const float* __restrict__ p01 = base + ((size_t)iy0 * IMG_W + ix1) * IMG_C;
    const float* __restrict__ p10 = base + ((size_t)iy1 * IMG_W + ix0) * IMG_C;
    const float* __restrict__ p11 = base + ((size_t)iy1 * IMG_W + ix1) * IMG_C;

    float* __restrict__ o = out + (size_t)idx * IMG_C + chunk_off + lane * 8;

    // Front-batched corner loads (warp-uniform predication on dead corners).
    u64 g00a, g00b, g00c, g00d;
    ldg256_cg(p00, g00a, g00b, g00c, g00d);

    u64 g01a = 0, g01b = 0, g01c = 0, g01d = 0;
    if (need_x1) ldg256_cg(p01, g01a, g01b, g01c, g01d);

    u64 g10a = 0, g10b = 0, g10c = 0, g10d = 0;
    u64 g11a = 0, g11b = 0, g11c = 0, g11d = 0;
    if (need_y1) {
        ldg256_cg(p10, g10a, g10b, g10c, g10d);
        if (need_x1) ldg256_cg(p11, g11a, g11b, g11c, g11d);
    }

#define XLERP(g0, g1) fma2(g1, wx2, mul2(g0, omwx2))

    // top row x-lerp (passthrough when wx==0 — exact, ref multiplies by 0)
    const u64 ta = need_x1 ? XLERP(g00a, g01a) : g00a;
    const u64 tb = need_x1 ? XLERP(g00b, g01b) : g00b;
    const u64 tc = need_x1 ? XLERP(g00c, g01c) : g00c;
    const u64 td = need_x1 ? XLERP(g00d, g01d) : g00d;

    // bottom row x-lerp (bot==top when wy==0 — exact)
    const u64 ba = need_y1 ? (need_x1 ? XLERP(g10a, g11a) : g10a) : ta;
    const u64 bb = need_y1 ? (need_x1 ? XLERP(g10b, g11b) : g10b) : tb;
    const u64 bc = need_y1 ? (need_x1 ? XLERP(g10c, g11c) : g10c) : tc;
    const u64 bd = need_y1 ? (need_x1 ? XLERP(g10d, g11d) : g10d) : td;

    // y-lerp
    const u64 r0 = fma2(ba, wy2, mul2(ta, omwy2));
    const u64 r1 = fma2(bb, wy2, mul2(tb, omwy2));
    const u64 r2 = fma2(bc, wy2, mul2(tc, omwy2));
    const u64 r3 = fma2(bd, wy2, mul2(td, omwy2));
#undef XLERP

    stg256_cs(o, r0, r1, r2, r3);
}

extern "C" void kernel_launch(void* const* d_in, const int* in_sizes, int n_in,
                              void* d_out, int out_size)
{
    const float* img  = (const float*)d_in[0];
    const int*   rois = (const int*)d_in[1];
    if (in_sizes[0] == NUM_ROIS * 4) {  // defensive: swapped order
        rois = (const int*)d_in[0];
        img  = (const float*)d_in[1];
    }
    float* out = (float*)d_out;

    dim3 grid((NUM_ROIS * POOL * POOL) / WARPS_PER_BLOCK, NCHUNK);  // (12544, 4)
    roi_resize_kernel<<<grid, THREADS>>>(img, rois, out);
}